// round 6
// baseline (speedup 1.0000x reference)
#include <cuda_runtime.h>
#include <cuda_fp16.h>
#include <mma.h>
#include <cstdint>

using namespace nvcuda;

#define NN 50000
#define NE 800000
#define NB_SCAN 49   // ceil(50000/1024)

// ---------------- scratch (static device allocations; no cudaMalloc) ----------------
// g_cnt[NN] counts; g_cnt[NN .. NN+64) lookback flags; g_cnt[NN+64 .. NN+128) block aggs.
__device__ int   g_cnt[NN + 128];
__device__ int   g_rowptr[NN + 1];
__device__ int   g_fill[NN];
__device__ int   g_colsrc[NE];
__device__ float g_dinv[NN];
__device__ __align__(16) __half g_u[(size_t)NN * 128];  // pre-agg messages (fp16)
__device__ __align__(16) __half g_h[(size_t)NN * 128];  // post-agg activations (fp16)

// ---------------- CSR build ----------------
__global__ void k_count(const int* __restrict__ ei) {
    int e = blockIdx.x * blockDim.x + threadIdx.x;
    if (e < NE) atomicAdd(&g_cnt[ei[NE + e]], 1);
}

// one-pass scan: 49 blocks x 1024 threads; all blocks co-resident -> spin-wait safe
__global__ void k_scanfull() {
    __shared__ int s[1024];
    __shared__ int sprefix;
    int b = blockIdx.x, t = threadIdx.x;
    int i = b * 1024 + t;
    int v = (i < NN) ? g_cnt[i] : 0;
    if (i < NN) g_dinv[i] = rsqrtf((float)(v + 1));  // +1 self loop
    s[t] = v;
    __syncthreads();
    #pragma unroll
    for (int off = 1; off < 1024; off <<= 1) {
        int add = (t >= off) ? s[t - off] : 0;
        __syncthreads();
        s[t] += add;
        __syncthreads();
    }
    int incl = s[t];
    if (t == 0) {
        g_cnt[NN + 64 + b] = s[1023];          // block aggregate
        __threadfence();
        ((volatile int*)(g_cnt + NN))[b] = 1;  // publish flag
    }
    if (t < 32) {
        int sum = 0;
        for (int p = t; p < b; p += 32) {
            while (((volatile int*)(g_cnt + NN))[p] == 0) {}
            sum += g_cnt[NN + 64 + p];
        }
        #pragma unroll
        for (int off = 16; off; off >>= 1) sum += __shfl_xor_sync(0xFFFFFFFFu, sum, off);
        if (t == 0) sprefix = sum;
    }
    __syncthreads();
    int pref = sprefix;
    if (i < NN) {
        int r = pref + incl - v;  // exclusive prefix
        g_rowptr[i] = r;
        g_fill[i] = r;
    }
    if (b == NB_SCAN - 1 && t == 1023) g_rowptr[NN] = pref + incl;  // == NE
}

__global__ void k_scatter(const int* __restrict__ ei) {
    int e = blockIdx.x * blockDim.x + threadIdx.x;
    if (e < NE) {
        int s = ei[e];
        int d = ei[NE + e];
        int pos = atomicAdd(&g_fill[d], 1);
        g_colsrc[pos] = s;
    }
}

// ---------------- wmma fp16 GEMM with register-prefetch pipeline ----------------
// U[128-tile, FOUT] = A @ W (fp32 accum -> fp16 out). K chunked by 32, next chunk
// prefetched into registers before the mma phase so DRAM latency overlaps tensor work.
template <int FIN, int FOUT, bool AFP32>
__global__ void __launch_bounds__(256) k_gemm_wmma(const float* __restrict__ Af32,
                                                   const float* __restrict__ W) {
    __shared__ __align__(16) __half As[128][40];
    __shared__ __align__(16) __half Bs[32][FOUT + 8];
    __shared__ __align__(16) float  Cs[8][16][20];

    constexpr int NBI = FOUT / 64;  // B-chunk load iterations per thread (2 for 128, 1 for 64)

    int tid = threadIdx.x, wid = tid >> 5, lane = tid & 31;
    int row0 = blockIdx.x * 128;

    // A-load geometry: thread covers row r, halves [c0, c0+16)
    int ar = tid >> 1, ac0 = (tid & 1) * 16;
    int gr = row0 + ar;

    wmma::fragment<wmma::accumulator, 16, 16, 16, float> acc[FOUT / 16];
    #pragma unroll
    for (int j = 0; j < FOUT / 16; j++) wmma::fill_fragment(acc[j], 0.0f);

    // prefetch registers
    float4 pa_f[4];          // AFP32 path: 16 floats
    uint4  pa_h[2];          // fp16 path: 16 halves
    float4 pb[NBI][2];       // B: NBI iterations x 8 floats

    auto loadA = [&](int k0) {
        if (gr < NN) {
            if (AFP32) {
                const float* src = Af32 + (size_t)gr * FIN + k0 + ac0;
                pa_f[0] = *(const float4*)(src + 0);
                pa_f[1] = *(const float4*)(src + 4);
                pa_f[2] = *(const float4*)(src + 8);
                pa_f[3] = *(const float4*)(src + 12);
            } else {
                const uint4* src = (const uint4*)(g_h + (size_t)gr * FIN + k0 + ac0);
                pa_h[0] = src[0];
                pa_h[1] = src[1];
            }
        } else {
            if (AFP32) { pa_f[0] = pa_f[1] = pa_f[2] = pa_f[3] = make_float4(0, 0, 0, 0); }
            else       { pa_h[0] = pa_h[1] = make_uint4(0, 0, 0, 0); }
        }
    };
    auto loadB = [&](int k0) {
        #pragma unroll
        for (int it = 0; it < NBI; it++) {
            int idx = tid + it * 256;
            int r = idx / (FOUT / 8);
            int cb = (idx % (FOUT / 8)) * 8;
            const float* src = W + (size_t)(k0 + r) * FOUT + cb;
            pb[it][0] = *(const float4*)(src + 0);
            pb[it][1] = *(const float4*)(src + 4);
        }
    };
    auto storeA = [&]() {
        uint4 p0, p1;
        if (AFP32) {
            __half2 h0 = __floats2half2_rn(pa_f[0].x, pa_f[0].y), h1 = __floats2half2_rn(pa_f[0].z, pa_f[0].w);
            __half2 h2 = __floats2half2_rn(pa_f[1].x, pa_f[1].y), h3 = __floats2half2_rn(pa_f[1].z, pa_f[1].w);
            __half2 h4 = __floats2half2_rn(pa_f[2].x, pa_f[2].y), h5 = __floats2half2_rn(pa_f[2].z, pa_f[2].w);
            __half2 h6 = __floats2half2_rn(pa_f[3].x, pa_f[3].y), h7 = __floats2half2_rn(pa_f[3].z, pa_f[3].w);
            p0 = make_uint4(*(uint32_t*)&h0, *(uint32_t*)&h1, *(uint32_t*)&h2, *(uint32_t*)&h3);
            p1 = make_uint4(*(uint32_t*)&h4, *(uint32_t*)&h5, *(uint32_t*)&h6, *(uint32_t*)&h7);
        } else {
            p0 = pa_h[0];
            p1 = pa_h[1];
        }
        *(uint4*)&As[ar][ac0]     = p0;
        *(uint4*)&As[ar][ac0 + 8] = p1;
    };
    auto storeB = [&]() {
        #pragma unroll
        for (int it = 0; it < NBI; it++) {
            int idx = tid + it * 256;
            int r = idx / (FOUT / 8);
            int cb = (idx % (FOUT / 8)) * 8;
            __half2 h0 = __floats2half2_rn(pb[it][0].x, pb[it][0].y);
            __half2 h1 = __floats2half2_rn(pb[it][0].z, pb[it][0].w);
            __half2 h2 = __floats2half2_rn(pb[it][1].x, pb[it][1].y);
            __half2 h3 = __floats2half2_rn(pb[it][1].z, pb[it][1].w);
            *(uint4*)&Bs[r][cb] =
                make_uint4(*(uint32_t*)&h0, *(uint32_t*)&h1, *(uint32_t*)&h2, *(uint32_t*)&h3);
        }
    };

    loadA(0);
    loadB(0);

    #pragma unroll
    for (int k0 = 0; k0 < FIN; k0 += 32) {
        storeA();
        storeB();
        __syncthreads();
        if (k0 + 32 < FIN) {  // issue next chunk's global loads before mma
            loadA(k0 + 32);
            loadB(k0 + 32);
        }
        #pragma unroll
        for (int kk = 0; kk < 32; kk += 16) {
            wmma::fragment<wmma::matrix_a, 16, 16, 16, __half, wmma::row_major> af;
            wmma::load_matrix_sync(af, &As[wid * 16][kk], 40);
            #pragma unroll
            for (int j = 0; j < FOUT / 16; j++) {
                wmma::fragment<wmma::matrix_b, 16, 16, 16, __half, wmma::row_major> bf;
                wmma::load_matrix_sync(bf, &Bs[kk][j * 16], FOUT + 8);
                wmma::mma_sync(acc[j], af, bf, acc[j]);
            }
        }
        __syncthreads();
    }

    #pragma unroll
    for (int j = 0; j < FOUT / 16; j++) {
        wmma::store_matrix_sync(&Cs[wid][0][0], acc[j], 20, wmma::mem_row_major);
        __syncwarp();
        int r = lane >> 1, c0 = (lane & 1) * 8;
        int grr = row0 + wid * 16 + r;
        if (grr < NN) {
            const float* s = &Cs[wid][r][c0];
            __half2 h0 = __floats2half2_rn(s[0], s[1]);
            __half2 h1 = __floats2half2_rn(s[2], s[3]);
            __half2 h2 = __floats2half2_rn(s[4], s[5]);
            __half2 h3 = __floats2half2_rn(s[6], s[7]);
            *(uint4*)(g_u + (size_t)grr * FOUT + j * 16 + c0) =
                make_uint4(*(uint32_t*)&h0, *(uint32_t*)&h1, *(uint32_t*)&h2, *(uint32_t*)&h3);
        }
        __syncwarp();
    }
}

// ---------------- CSR gather aggregation (fp16 in/out, fp32 accum) ----------------
__device__ __forceinline__ void acc4(float4& a, uint2 v, float d) {
    float2 f0 = __half22float2(*(__half2*)&v.x);
    float2 f1 = __half22float2(*(__half2*)&v.y);
    a.x = fmaf(f0.x, d, a.x); a.y = fmaf(f0.y, d, a.y);
    a.z = fmaf(f1.x, d, a.z); a.w = fmaf(f1.y, d, a.w);
}

__global__ void k_agg128(const float* __restrict__ bias) {
    int w = (blockIdx.x * blockDim.x + threadIdx.x) >> 5;
    int lane = threadIdx.x & 31;
    if (w >= NN) return;
    const uint2* Uv = (const uint2*)g_u;
    float dd = g_dinv[w];
    float4 acc = make_float4(0.f, 0.f, 0.f, 0.f);
    acc4(acc, Uv[(size_t)w * 32 + lane], dd);
    int e0 = g_rowptr[w], e1 = g_rowptr[w + 1];
    int e = e0;
    for (; e + 4 <= e1; e += 4) {
        int s0 = g_colsrc[e], s1 = g_colsrc[e + 1], s2 = g_colsrc[e + 2], s3 = g_colsrc[e + 3];
        float d0 = g_dinv[s0], d1 = g_dinv[s1], d2 = g_dinv[s2], d3 = g_dinv[s3];
        uint2 v0 = Uv[(size_t)s0 * 32 + lane];
        uint2 v1 = Uv[(size_t)s1 * 32 + lane];
        uint2 v2 = Uv[(size_t)s2 * 32 + lane];
        uint2 v3 = Uv[(size_t)s3 * 32 + lane];
        acc4(acc, v0, d0); acc4(acc, v1, d1); acc4(acc, v2, d2); acc4(acc, v3, d3);
    }
    for (; e < e1; e++) {
        int s = g_colsrc[e];
        acc4(acc, Uv[(size_t)s * 32 + lane], g_dinv[s]);
    }
    float4 bb = ((const float4*)bias)[lane];
    __half2 o0 = __floats2half2_rn(fmaxf(fmaf(acc.x, dd, bb.x), 0.f),
                                   fmaxf(fmaf(acc.y, dd, bb.y), 0.f));
    __half2 o1 = __floats2half2_rn(fmaxf(fmaf(acc.z, dd, bb.z), 0.f),
                                   fmaxf(fmaf(acc.w, dd, bb.w), 0.f));
    ((uint2*)g_h)[(size_t)w * 32 + lane] = make_uint2(*(uint32_t*)&o0, *(uint32_t*)&o1);
}

__global__ void k_agg64(const float* __restrict__ bias) {
    int w = (blockIdx.x * blockDim.x + threadIdx.x) >> 5;
    int lane = threadIdx.x & 31;
    if (w >= NN) return;
    const uint32_t* Uv = (const uint32_t*)g_u;
    float dd = g_dinv[w];
    float2 acc;
    {
        float2 f = __half22float2(*(__half2*)&Uv[(size_t)w * 32 + lane]);
        acc.x = f.x * dd; acc.y = f.y * dd;
    }
    int e0 = g_rowptr[w], e1 = g_rowptr[w + 1];
    int e = e0;
    for (; e + 4 <= e1; e += 4) {
        int s0 = g_colsrc[e], s1 = g_colsrc[e + 1], s2 = g_colsrc[e + 2], s3 = g_colsrc[e + 3];
        float d0 = g_dinv[s0], d1 = g_dinv[s1], d2 = g_dinv[s2], d3 = g_dinv[s3];
        uint32_t v0 = Uv[(size_t)s0 * 32 + lane];
        uint32_t v1 = Uv[(size_t)s1 * 32 + lane];
        uint32_t v2 = Uv[(size_t)s2 * 32 + lane];
        uint32_t v3 = Uv[(size_t)s3 * 32 + lane];
        float2 f0 = __half22float2(*(__half2*)&v0);
        float2 f1 = __half22float2(*(__half2*)&v1);
        float2 f2 = __half22float2(*(__half2*)&v2);
        float2 f3 = __half22float2(*(__half2*)&v3);
        acc.x = fmaf(f0.x, d0, acc.x); acc.y = fmaf(f0.y, d0, acc.y);
        acc.x = fmaf(f1.x, d1, acc.x); acc.y = fmaf(f1.y, d1, acc.y);
        acc.x = fmaf(f2.x, d2, acc.x); acc.y = fmaf(f2.y, d2, acc.y);
        acc.x = fmaf(f3.x, d3, acc.x); acc.y = fmaf(f3.y, d3, acc.y);
    }
    for (; e < e1; e++) {
        int s = g_colsrc[e];
        float2 f = __half22float2(*(__half2*)&Uv[(size_t)s * 32 + lane]);
        float d = g_dinv[s];
        acc.x = fmaf(f.x, d, acc.x); acc.y = fmaf(f.y, d, acc.y);
    }
    float2 bb = ((const float2*)bias)[lane];
    __half2 o = __floats2half2_rn(fmaxf(fmaf(acc.x, dd, bb.x), 0.f),
                                  fmaxf(fmaf(acc.y, dd, bb.y), 0.f));
    ((uint32_t*)g_h)[(size_t)w * 32 + lane] = *(uint32_t*)&o;
}

// ---------------- fused: agg (layer 3) + prototype head + MLP + sigmoid + y copy ----------------
__device__ __forceinline__ float gelu_exact(float x) {
    return 0.5f * x * (1.0f + erff(x * 0.70710678118654752f));
}

__global__ void k_agg64_head(const float* __restrict__ bias,
                             const float* __restrict__ prot,
                             const float* __restrict__ Wf0, const float* __restrict__ bf0,
                             const float* __restrict__ Wf1, const float* __restrict__ bf1,
                             const int* __restrict__ y,
                             float* __restrict__ out, int out_size) {
    __shared__ float ps[16][64];
    __shared__ float pn[16];
    __shared__ float w0s[16][8];
    __shared__ float b0s[8];
    __shared__ float w1s[8];
    __shared__ float b1s;

    int tid = threadIdx.x;
    for (int i = tid; i < 16 * 64; i += blockDim.x) ps[i >> 6][i & 63] = prot[i];
    if (tid < 16 * 8) w0s[tid >> 3][tid & 7] = Wf0[tid];
    if (tid < 8) { b0s[tid] = bf0[tid]; w1s[tid] = Wf1[tid]; }
    if (tid == 0) b1s = bf1[0];
    __syncthreads();
    if (tid < 16) {
        float s = 0.f;
        #pragma unroll
        for (int c = 0; c < 64; c++) s += ps[tid][c] * ps[tid][c];
        pn[tid] = s;
    }
    __syncthreads();

    int w = (blockIdx.x * blockDim.x + tid) >> 5;
    int lane = tid & 31;
    if (w >= NN) return;

    // ---- aggregation (layer 3) ----
    const uint32_t* Uv = (const uint32_t*)g_u;
    float dd = g_dinv[w];
    float2 acc;
    {
        float2 f = __half22float2(*(__half2*)&Uv[(size_t)w * 32 + lane]);
        acc.x = f.x * dd; acc.y = f.y * dd;
    }
    int e0 = g_rowptr[w], e1 = g_rowptr[w + 1];
    int e = e0;
    for (; e + 4 <= e1; e += 4) {
        int s0 = g_colsrc[e], s1 = g_colsrc[e + 1], s2 = g_colsrc[e + 2], s3 = g_colsrc[e + 3];
        float d0 = g_dinv[s0], d1 = g_dinv[s1], d2 = g_dinv[s2], d3 = g_dinv[s3];
        uint32_t v0 = Uv[(size_t)s0 * 32 + lane];
        uint32_t v1 = Uv[(size_t)s1 * 32 + lane];
        uint32_t v2 = Uv[(size_t)s2 * 32 + lane];
        uint32_t v3 = Uv[(size_t)s3 * 32 + lane];
        float2 f0 = __half22float2(*(__half2*)&v0);
        float2 f1 = __half22float2(*(__half2*)&v1);
        float2 f2 = __half22float2(*(__half2*)&v2);
        float2 f3 = __half22float2(*(__half2*)&v3);
        acc.x = fmaf(f0.x, d0, acc.x); acc.y = fmaf(f0.y, d0, acc.y);
        acc.x = fmaf(f1.x, d1, acc.x); acc.y = fmaf(f1.y, d1, acc.y);
        acc.x = fmaf(f2.x, d2, acc.x); acc.y = fmaf(f2.y, d2, acc.y);
        acc.x = fmaf(f3.x, d3, acc.x); acc.y = fmaf(f3.y, d3, acc.y);
    }
    for (; e < e1; e++) {
        int s = g_colsrc[e];
        float2 f = __half22float2(*(__half2*)&Uv[(size_t)s * 32 + lane]);
        float d = g_dinv[s];
        acc.x = fmaf(f.x, d, acc.x); acc.y = fmaf(f.y, d, acc.y);
    }
    float2 bb = ((const float2*)bias)[lane];
    float h0 = fmaxf(fmaf(acc.x, dd, bb.x), 0.f);  // h3 cols {2*lane, 2*lane+1}
    float h1 = fmaxf(fmaf(acc.y, dd, bb.y), 0.f);

    // ---- head: squared distance to 16 prototypes, warp butterfly reductions ----
    float hh = h0 * h0 + h1 * h1;
    #pragma unroll
    for (int off = 16; off; off >>= 1) hh += __shfl_xor_sync(0xFFFFFFFFu, hh, off);

    float sim[16];
    #pragma unroll
    for (int k = 0; k < 16; k++) {
        float2 p = *(float2*)&ps[k][2 * lane];
        float dot = h0 * p.x + h1 * p.y;
        #pragma unroll
        for (int off = 16; off; off >>= 1) dot += __shfl_xor_sync(0xFFFFFFFFu, dot, off);
        float d2 = fmaxf(hh + pn[k] - 2.0f * dot, 0.f);
        sim[k] = __logf((d2 + 1.0f) / (d2 + 1e-4f));
    }

    // ---- MLP: lanes 0..7 each compute one hidden unit, reduce across 8 lanes ----
    float g = 0.f;
    if (lane < 8) {
        float z = b0s[lane];
        #pragma unroll
        for (int k = 0; k < 16; k++) z = fmaf(sim[k], w0s[k][lane], z);
        g = gelu_exact(z) * w1s[lane];
    }
    g += __shfl_down_sync(0xFFFFFFFFu, g, 4, 8);
    g += __shfl_down_sync(0xFFFFFFFFu, g, 2, 8);
    g += __shfl_down_sync(0xFFFFFFFFu, g, 1, 8);
    if (lane == 0) out[w] = 1.0f / (1.0f + expf(-(g + b1s)));
    if (lane == 1 && NN + w < out_size) out[NN + w] = (float)y[w];
}

// ---------------- launch (single stream) ----------------
extern "C" void kernel_launch(void* const* d_in, const int* in_sizes, int n_in,
                              void* d_out, int out_size) {
    const float* x    = (const float*)d_in[0];
    const int*   ei   = (const int*)d_in[1];
    const int*   y    = (const int*)d_in[2];
    const float* W1   = (const float*)d_in[3];
    const float* b1   = (const float*)d_in[4];
    const float* W2   = (const float*)d_in[5];
    const float* b2   = (const float*)d_in[6];
    const float* W3   = (const float*)d_in[7];
    const float* b3   = (const float*)d_in[8];
    const float* prot = (const float*)d_in[9];
    const float* Wf0  = (const float*)d_in[10];
    const float* bf0  = (const float*)d_in[11];
    const float* Wf1  = (const float*)d_in[12];
    const float* bf1  = (const float*)d_in[13];
    float* out = (float*)d_out;

    static void* cntPtr = nullptr;
    if (!cntPtr) cudaGetSymbolAddress(&cntPtr, g_cnt);

    const int MT = (NN + 127) / 128;           // 391 M-tiles
    int aggBlocks = (NN * 32 + 255) / 256;

    // CSR build
    cudaMemsetAsync(cntPtr, 0, sizeof(int) * (NN + 128), 0);
    k_count<<<(NE + 255) / 256, 256>>>(ei);
    k_scanfull<<<NB_SCAN, 1024>>>();
    k_scatter<<<(NE + 255) / 256, 256>>>(ei);

    // layer 1 -> 2 -> 3 -> fused head
    k_gemm_wmma<128, 128, true><<<MT, 256>>>(x, W1);
    k_agg128<<<aggBlocks, 256>>>(b1);
    k_gemm_wmma<128, 64, false><<<MT, 256>>>(nullptr, W2);
    k_agg64<<<aggBlocks, 256>>>(b2);
    k_gemm_wmma<64, 64, false><<<MT, 256>>>(nullptr, W3);
    k_agg64_head<<<aggBlocks, 256>>>(b3, prot, Wf0, bf0, Wf1, bf1, y, out, out_size);
}

// round 7
// speedup vs baseline: 1.1824x; 1.1824x over previous
#include <cuda_runtime.h>
#include <cuda_fp16.h>
#include <mma.h>
#include <cstdint>

using namespace nvcuda;

#define NN 50000
#define NE 800000
#define SCAN_B 1024
#define SCAN_NB ((NN + SCAN_B - 1) / SCAN_B)

// ---------------- scratch (static device allocations; no cudaMalloc) ----------------
__device__ int   g_cnt[NN];
__device__ int   g_rowptr[NN + 1];
__device__ int   g_fill[NN];
__device__ int   g_colsrc[NE];
__device__ float g_dinv[NN];
__device__ int   g_bsum[64];
__device__ __align__(16) __half g_u[(size_t)NN * 128];  // pre-agg messages (fp16)
__device__ __align__(16) __half g_h[(size_t)NN * 128];  // post-agg activations (fp16)

// ---------------- degree / CSR build ----------------
__global__ void k_zero_cnt() {
    int i = blockIdx.x * blockDim.x + threadIdx.x;
    if (i < NN) g_cnt[i] = 0;
}

__global__ void k_count(const int* __restrict__ ei) {
    int e = blockIdx.x * blockDim.x + threadIdx.x;
    if (e < NE) atomicAdd(&g_cnt[ei[NE + e]], 1);
}

__global__ void k_scan1() {
    __shared__ int s[SCAN_B];
    int t = threadIdx.x;
    int i = blockIdx.x * SCAN_B + t;
    int v = (i < NN) ? g_cnt[i] : 0;
    if (i < NN) g_dinv[i] = rsqrtf((float)(v + 1));  // self loop included in degree
    s[t] = v;
    __syncthreads();
    #pragma unroll
    for (int off = 1; off < SCAN_B; off <<= 1) {
        int add = (t >= off) ? s[t - off] : 0;
        __syncthreads();
        s[t] += add;
        __syncthreads();
    }
    if (i < NN) g_rowptr[i] = s[t] - v;  // exclusive within block
    if (t == SCAN_B - 1) g_bsum[blockIdx.x] = s[t];
}

__global__ void k_scan2() {  // 64 threads, scan 49 block sums
    __shared__ int s[64];
    int t = threadIdx.x;
    int v = (t < SCAN_NB) ? g_bsum[t] : 0;
    s[t] = v;
    __syncthreads();
    #pragma unroll
    for (int off = 1; off < 64; off <<= 1) {
        int add = (t >= off) ? s[t - off] : 0;
        __syncthreads();
        s[t] += add;
        __syncthreads();
    }
    if (t < SCAN_NB) g_bsum[t] = s[t] - v;      // exclusive
    if (t == SCAN_NB - 1) g_rowptr[NN] = s[t];  // total == NE
}

__global__ void k_scan3() {
    int i = blockIdx.x * SCAN_B + threadIdx.x;
    if (i < NN) {
        int r = g_rowptr[i] + g_bsum[blockIdx.x];
        g_rowptr[i] = r;
        g_fill[i] = r;
    }
}

__global__ void k_scatter(const int* __restrict__ ei) {
    int e = blockIdx.x * blockDim.x + threadIdx.x;
    if (e < NE) {
        int s = ei[e];
        int d = ei[NE + e];
        int pos = atomicAdd(&g_fill[d], 1);
        g_colsrc[pos] = s;
    }
}

// ---------------- wmma fp16 GEMM with register-prefetch pipeline ----------------
// U[128-tile, FOUT] = A @ W (fp32 accum -> fp16 out). K chunked by 32, next chunk
// prefetched into registers before the mma phase so DRAM latency overlaps tensor work.
template <int FIN, int FOUT, bool AFP32>
__global__ void __launch_bounds__(256) k_gemm_wmma(const float* __restrict__ Af32,
                                                   const float* __restrict__ W) {
    __shared__ __align__(16) __half As[128][40];
    __shared__ __align__(16) __half Bs[32][FOUT + 8];
    __shared__ __align__(16) float  Cs[8][16][20];

    constexpr int NBI = FOUT / 64;  // B-chunk load iterations per thread

    int tid = threadIdx.x, wid = tid >> 5, lane = tid & 31;
    int row0 = blockIdx.x * 128;

    int ar = tid >> 1, ac0 = (tid & 1) * 16;
    int gr = row0 + ar;

    wmma::fragment<wmma::accumulator, 16, 16, 16, float> acc[FOUT / 16];
    #pragma unroll
    for (int j = 0; j < FOUT / 16; j++) wmma::fill_fragment(acc[j], 0.0f);

    float4 pa_f[4];
    uint4  pa_h[2];
    float4 pb[NBI][2];

    auto loadA = [&](int k0) {
        if (gr < NN) {
            if (AFP32) {
                const float* src = Af32 + (size_t)gr * FIN + k0 + ac0;
                pa_f[0] = *(const float4*)(src + 0);
                pa_f[1] = *(const float4*)(src + 4);
                pa_f[2] = *(const float4*)(src + 8);
                pa_f[3] = *(const float4*)(src + 12);
            } else {
                const uint4* src = (const uint4*)(g_h + (size_t)gr * FIN + k0 + ac0);
                pa_h[0] = src[0];
                pa_h[1] = src[1];
            }
        } else {
            if (AFP32) { pa_f[0] = pa_f[1] = pa_f[2] = pa_f[3] = make_float4(0, 0, 0, 0); }
            else       { pa_h[0] = pa_h[1] = make_uint4(0, 0, 0, 0); }
        }
    };
    auto loadB = [&](int k0) {
        #pragma unroll
        for (int it = 0; it < NBI; it++) {
            int idx = tid + it * 256;
            int r = idx / (FOUT / 8);
            int cb = (idx % (FOUT / 8)) * 8;
            const float* src = W + (size_t)(k0 + r) * FOUT + cb;
            pb[it][0] = *(const float4*)(src + 0);
            pb[it][1] = *(const float4*)(src + 4);
        }
    };
    auto storeA = [&]() {
        uint4 p0, p1;
        if (AFP32) {
            __half2 h0 = __floats2half2_rn(pa_f[0].x, pa_f[0].y), h1 = __floats2half2_rn(pa_f[0].z, pa_f[0].w);
            __half2 h2 = __floats2half2_rn(pa_f[1].x, pa_f[1].y), h3 = __floats2half2_rn(pa_f[1].z, pa_f[1].w);
            __half2 h4 = __floats2half2_rn(pa_f[2].x, pa_f[2].y), h5 = __floats2half2_rn(pa_f[2].z, pa_f[2].w);
            __half2 h6 = __floats2half2_rn(pa_f[3].x, pa_f[3].y), h7 = __floats2half2_rn(pa_f[3].z, pa_f[3].w);
            p0 = make_uint4(*(uint32_t*)&h0, *(uint32_t*)&h1, *(uint32_t*)&h2, *(uint32_t*)&h3);
            p1 = make_uint4(*(uint32_t*)&h4, *(uint32_t*)&h5, *(uint32_t*)&h6, *(uint32_t*)&h7);
        } else {
            p0 = pa_h[0];
            p1 = pa_h[1];
        }
        *(uint4*)&As[ar][ac0]     = p0;
        *(uint4*)&As[ar][ac0 + 8] = p1;
    };
    auto storeB = [&]() {
        #pragma unroll
        for (int it = 0; it < NBI; it++) {
            int idx = tid + it * 256;
            int r = idx / (FOUT / 8);
            int cb = (idx % (FOUT / 8)) * 8;
            __half2 h0 = __floats2half2_rn(pb[it][0].x, pb[it][0].y);
            __half2 h1 = __floats2half2_rn(pb[it][0].z, pb[it][0].w);
            __half2 h2 = __floats2half2_rn(pb[it][1].x, pb[it][1].y);
            __half2 h3 = __floats2half2_rn(pb[it][1].z, pb[it][1].w);
            *(uint4*)&Bs[r][cb] =
                make_uint4(*(uint32_t*)&h0, *(uint32_t*)&h1, *(uint32_t*)&h2, *(uint32_t*)&h3);
        }
    };

    loadA(0);
    loadB(0);

    #pragma unroll
    for (int k0 = 0; k0 < FIN; k0 += 32) {
        storeA();
        storeB();
        __syncthreads();
        if (k0 + 32 < FIN) {  // issue next chunk's global loads before mma
            loadA(k0 + 32);
            loadB(k0 + 32);
        }
        #pragma unroll
        for (int kk = 0; kk < 32; kk += 16) {
            wmma::fragment<wmma::matrix_a, 16, 16, 16, __half, wmma::row_major> af;
            wmma::load_matrix_sync(af, &As[wid * 16][kk], 40);
            #pragma unroll
            for (int j = 0; j < FOUT / 16; j++) {
                wmma::fragment<wmma::matrix_b, 16, 16, 16, __half, wmma::row_major> bf;
                wmma::load_matrix_sync(bf, &Bs[kk][j * 16], FOUT + 8);
                wmma::mma_sync(acc[j], af, bf, acc[j]);
            }
        }
        __syncthreads();
    }

    #pragma unroll
    for (int j = 0; j < FOUT / 16; j++) {
        wmma::store_matrix_sync(&Cs[wid][0][0], acc[j], 20, wmma::mem_row_major);
        __syncwarp();
        int r = lane >> 1, c0 = (lane & 1) * 8;
        int grr = row0 + wid * 16 + r;
        if (grr < NN) {
            const float* s = &Cs[wid][r][c0];
            __half2 h0 = __floats2half2_rn(s[0], s[1]);
            __half2 h1 = __floats2half2_rn(s[2], s[3]);
            __half2 h2 = __floats2half2_rn(s[4], s[5]);
            __half2 h3 = __floats2half2_rn(s[6], s[7]);
            *(uint4*)(g_u + (size_t)grr * FOUT + j * 16 + c0) =
                make_uint4(*(uint32_t*)&h0, *(uint32_t*)&h1, *(uint32_t*)&h2, *(uint32_t*)&h3);
        }
        __syncwarp();
    }
}

// ---------------- CSR gather aggregation (fp16 in/out, fp32 accum) ----------------
__device__ __forceinline__ void acc4(float4& a, uint2 v, float d) {
    float2 f0 = __half22float2(*(__half2*)&v.x);
    float2 f1 = __half22float2(*(__half2*)&v.y);
    a.x = fmaf(f0.x, d, a.x); a.y = fmaf(f0.y, d, a.y);
    a.z = fmaf(f1.x, d, a.z); a.w = fmaf(f1.y, d, a.w);
}

__global__ void k_agg128(const float* __restrict__ bias) {
    int w = (blockIdx.x * blockDim.x + threadIdx.x) >> 5;
    int lane = threadIdx.x & 31;
    if (w >= NN) return;
    const uint2* Uv = (const uint2*)g_u;
    float dd = g_dinv[w];
    float4 acc = make_float4(0.f, 0.f, 0.f, 0.f);
    acc4(acc, Uv[(size_t)w * 32 + lane], dd);
    int e0 = g_rowptr[w], e1 = g_rowptr[w + 1];
    int e = e0;
    for (; e + 4 <= e1; e += 4) {
        int s0 = g_colsrc[e], s1 = g_colsrc[e + 1], s2 = g_colsrc[e + 2], s3 = g_colsrc[e + 3];
        float d0 = g_dinv[s0], d1 = g_dinv[s1], d2 = g_dinv[s2], d3 = g_dinv[s3];
        uint2 v0 = Uv[(size_t)s0 * 32 + lane];
        uint2 v1 = Uv[(size_t)s1 * 32 + lane];
        uint2 v2 = Uv[(size_t)s2 * 32 + lane];
        uint2 v3 = Uv[(size_t)s3 * 32 + lane];
        acc4(acc, v0, d0); acc4(acc, v1, d1); acc4(acc, v2, d2); acc4(acc, v3, d3);
    }
    for (; e < e1; e++) {
        int s = g_colsrc[e];
        acc4(acc, Uv[(size_t)s * 32 + lane], g_dinv[s]);
    }
    float4 bb = ((const float4*)bias)[lane];
    __half2 o0 = __floats2half2_rn(fmaxf(fmaf(acc.x, dd, bb.x), 0.f),
                                   fmaxf(fmaf(acc.y, dd, bb.y), 0.f));
    __half2 o1 = __floats2half2_rn(fmaxf(fmaf(acc.z, dd, bb.z), 0.f),
                                   fmaxf(fmaf(acc.w, dd, bb.w), 0.f));
    ((uint2*)g_h)[(size_t)w * 32 + lane] = make_uint2(*(uint32_t*)&o0, *(uint32_t*)&o1);
}

__global__ void k_agg64(const float* __restrict__ bias) {
    int w = (blockIdx.x * blockDim.x + threadIdx.x) >> 5;
    int lane = threadIdx.x & 31;
    if (w >= NN) return;
    const uint32_t* Uv = (const uint32_t*)g_u;
    float dd = g_dinv[w];
    float2 acc;
    {
        float2 f = __half22float2(*(__half2*)&Uv[(size_t)w * 32 + lane]);
        acc.x = f.x * dd; acc.y = f.y * dd;
    }
    int e0 = g_rowptr[w], e1 = g_rowptr[w + 1];
    int e = e0;
    for (; e + 4 <= e1; e += 4) {
        int s0 = g_colsrc[e], s1 = g_colsrc[e + 1], s2 = g_colsrc[e + 2], s3 = g_colsrc[e + 3];
        float d0 = g_dinv[s0], d1 = g_dinv[s1], d2 = g_dinv[s2], d3 = g_dinv[s3];
        uint32_t v0 = Uv[(size_t)s0 * 32 + lane];
        uint32_t v1 = Uv[(size_t)s1 * 32 + lane];
        uint32_t v2 = Uv[(size_t)s2 * 32 + lane];
        uint32_t v3 = Uv[(size_t)s3 * 32 + lane];
        float2 f0 = __half22float2(*(__half2*)&v0);
        float2 f1 = __half22float2(*(__half2*)&v1);
        float2 f2 = __half22float2(*(__half2*)&v2);
        float2 f3 = __half22float2(*(__half2*)&v3);
        acc.x = fmaf(f0.x, d0, acc.x); acc.y = fmaf(f0.y, d0, acc.y);
        acc.x = fmaf(f1.x, d1, acc.x); acc.y = fmaf(f1.y, d1, acc.y);
        acc.x = fmaf(f2.x, d2, acc.x); acc.y = fmaf(f2.y, d2, acc.y);
        acc.x = fmaf(f3.x, d3, acc.x); acc.y = fmaf(f3.y, d3, acc.y);
    }
    for (; e < e1; e++) {
        int s = g_colsrc[e];
        float2 f = __half22float2(*(__half2*)&Uv[(size_t)s * 32 + lane]);
        float d = g_dinv[s];
        acc.x = fmaf(f.x, d, acc.x); acc.y = fmaf(f.y, d, acc.y);
    }
    float2 bb = ((const float2*)bias)[lane];
    __half2 o = __floats2half2_rn(fmaxf(fmaf(acc.x, dd, bb.x), 0.f),
                                  fmaxf(fmaf(acc.y, dd, bb.y), 0.f));
    ((uint32_t*)g_h)[(size_t)w * 32 + lane] = *(uint32_t*)&o;
}

// ---------------- prototype-distance head + MLP + y copy ----------------
__device__ __forceinline__ float gelu_exact(float x) {
    return 0.5f * x * (1.0f + erff(x * 0.70710678118654752f));
}

__global__ void k_head(const float* __restrict__ prot,
                       const float* __restrict__ Wf0, const float* __restrict__ bf0,
                       const float* __restrict__ Wf1, const float* __restrict__ bf1,
                       const int* __restrict__ y,
                       float* __restrict__ out, int out_size) {
    __shared__ float hs[128][65];
    __shared__ float ps[16][64];
    __shared__ float pn[16];
    __shared__ float w0[16][8];
    __shared__ float b0[8];
    __shared__ float w1[8];
    __shared__ float b1s;

    int t = threadIdx.x;
    int nd0 = blockIdx.x * 128;

    for (int idx = t; idx < 128 * 64; idx += 128) {
        int r = idx >> 6, c = idx & 63;
        int node = nd0 + r;
        hs[r][c] = (node < NN) ? __half2float(g_h[(size_t)node * 64 + c]) : 0.f;
    }
    for (int idx = t; idx < 16 * 64; idx += 128)
        ps[idx >> 6][idx & 63] = prot[idx];
    if (t < 16 * 8) w0[t >> 3][t & 7] = Wf0[t];
    if (t < 8) { b0[t] = bf0[t]; w1[t] = Wf1[t]; }
    if (t == 0) b1s = bf1[0];
    __syncthreads();
    if (t < 16) {
        float s = 0.f;
        #pragma unroll
        for (int c = 0; c < 64; c++) s += ps[t][c] * ps[t][c];
        pn[t] = s;
    }
    __syncthreads();

    int node = nd0 + t;
    if (node < NN) {
        float hh = 0.f;
        #pragma unroll
        for (int c = 0; c < 64; c++) hh = fmaf(hs[t][c], hs[t][c], hh);

        float sim[16];
        #pragma unroll
        for (int k = 0; k < 16; k++) {
            float dot = 0.f;
            #pragma unroll
            for (int c = 0; c < 64; c++) dot = fmaf(hs[t][c], ps[k][c], dot);
            float d2 = fmaxf(hh + pn[k] - 2.0f * dot, 0.f);
            sim[k] = logf((d2 + 1.0f) / (d2 + 1e-4f));
        }

        float o = b1s;
        #pragma unroll
        for (int j = 0; j < 8; j++) {
            float z = b0[j];
            #pragma unroll
            for (int k = 0; k < 16; k++) z = fmaf(sim[k], w0[k][j], z);
            o = fmaf(gelu_exact(z), w1[j], o);
        }
        out[node] = 1.0f / (1.0f + expf(-o));
        if (NN + node < out_size) out[NN + node] = (float)y[node];
    }
}

// ---------------- launch (single stream, R4 structure) ----------------
extern "C" void kernel_launch(void* const* d_in, const int* in_sizes, int n_in,
                              void* d_out, int out_size) {
    const float* x    = (const float*)d_in[0];
    const int*   ei   = (const int*)d_in[1];
    const int*   y    = (const int*)d_in[2];
    const float* W1   = (const float*)d_in[3];
    const float* b1   = (const float*)d_in[4];
    const float* W2   = (const float*)d_in[5];
    const float* b2   = (const float*)d_in[6];
    const float* W3   = (const float*)d_in[7];
    const float* b3   = (const float*)d_in[8];
    const float* prot = (const float*)d_in[9];
    const float* Wf0  = (const float*)d_in[10];
    const float* bf0  = (const float*)d_in[11];
    const float* Wf1  = (const float*)d_in[12];
    const float* bf1  = (const float*)d_in[13];
    float* out = (float*)d_out;

    // CSR build
    k_zero_cnt<<<(NN + 255) / 256, 256>>>();
    k_count<<<(NE + 255) / 256, 256>>>(ei);
    k_scan1<<<SCAN_NB, SCAN_B>>>();
    k_scan2<<<1, 64>>>();
    k_scan3<<<SCAN_NB, SCAN_B>>>();
    k_scatter<<<(NE + 255) / 256, 256>>>(ei);

    const int MT = (NN + 127) / 128;  // 391 M-tiles
    int aggBlocks = (NN * 32 + 255) / 256;

    // layer 1: x -> U (fp16) -> h1
    k_gemm_wmma<128, 128, true><<<MT, 256>>>(x, W1);
    k_agg128<<<aggBlocks, 256>>>(b1);
    // layer 2: h1 -> U -> h2
    k_gemm_wmma<128, 64, false><<<MT, 256>>>(nullptr, W2);
    k_agg64<<<aggBlocks, 256>>>(b2);
    // layer 3: h2 -> U -> h3
    k_gemm_wmma<64, 64, false><<<MT, 256>>>(nullptr, W3);
    k_agg64<<<aggBlocks, 256>>>(b3);

    // head + y copy
    k_head<<<(NN + 127) / 128, 128>>>(prot, Wf0, bf0, Wf1, bf1, y, out, out_size);
}

// round 8
// speedup vs baseline: 1.2215x; 1.0331x over previous
#include <cuda_runtime.h>
#include <cuda_fp16.h>
#include <mma.h>
#include <cstdint>

using namespace nvcuda;

#define NN 50000
#define NE 800000
#define SCAN_B 1024
#define SCAN_NB ((NN + SCAN_B - 1) / SCAN_B)

// ---------------- scratch (static device allocations; no cudaMalloc) ----------------
__device__ int   g_cnt[NN];
__device__ int   g_rowptr[NN + 1];
__device__ int   g_fill[NN];
__device__ int   g_colsrc[NE];
__device__ float g_dinv[NN];
__device__ int   g_bsum[64];
__device__ __align__(16) __half g_u[(size_t)NN * 128];  // pre-agg messages (fp16)
__device__ __align__(16) __half g_h[(size_t)NN * 128];  // post-agg activations (fp16)

// ---------------- degree / CSR build ----------------
__global__ void k_count(const int* __restrict__ ei) {
    int e = blockIdx.x * blockDim.x + threadIdx.x;
    if (e < NE) atomicAdd(&g_cnt[ei[NE + e]], 1);
}

__global__ void k_scan1() {
    __shared__ int s[SCAN_B];
    int t = threadIdx.x;
    int i = blockIdx.x * SCAN_B + t;
    int v = (i < NN) ? g_cnt[i] : 0;
    if (i < NN) g_dinv[i] = rsqrtf((float)(v + 1));  // self loop included in degree
    s[t] = v;
    __syncthreads();
    #pragma unroll
    for (int off = 1; off < SCAN_B; off <<= 1) {
        int add = (t >= off) ? s[t - off] : 0;
        __syncthreads();
        s[t] += add;
        __syncthreads();
    }
    if (i < NN) g_rowptr[i] = s[t] - v;  // exclusive within block
    if (t == SCAN_B - 1) g_bsum[blockIdx.x] = s[t];
}

// merged scan2+scan3: each block reduces the preceding block sums itself
__global__ void k_scan3() {
    __shared__ int spref;
    int b = blockIdx.x, t = threadIdx.x;
    if (t < 32) {
        int sum = 0;
        for (int p = t; p < b; p += 32) sum += g_bsum[p];
        #pragma unroll
        for (int off = 16; off; off >>= 1) sum += __shfl_xor_sync(0xFFFFFFFFu, sum, off);
        if (t == 0) spref = sum;
    }
    __syncthreads();
    int i = b * SCAN_B + t;
    if (i < NN) {
        int r = g_rowptr[i] + spref;
        g_rowptr[i] = r;
        g_fill[i] = r;
    }
    if (b == 0 && t == 0) g_rowptr[NN] = NE;  // total is a compile-time constant
}

__global__ void k_scatter(const int* __restrict__ ei) {
    int e = blockIdx.x * blockDim.x + threadIdx.x;
    if (e < NE) {
        int s = ei[e];
        int d = ei[NE + e];
        int pos = atomicAdd(&g_fill[d], 1);
        g_colsrc[pos] = s;
    }
}

// ---------------- wmma fp16 GEMM with register-prefetch pipeline ----------------
template <int FIN, int FOUT, bool AFP32>
__global__ void __launch_bounds__(256) k_gemm_wmma(const float* __restrict__ Af32,
                                                   const float* __restrict__ W) {
    __shared__ __align__(16) __half As[128][40];
    __shared__ __align__(16) __half Bs[32][FOUT + 8];
    __shared__ __align__(16) float  Cs[8][16][20];

    constexpr int NBI = FOUT / 64;  // B-chunk load iterations per thread

    int tid = threadIdx.x, wid = tid >> 5, lane = tid & 31;
    int row0 = blockIdx.x * 128;

    int ar = tid >> 1, ac0 = (tid & 1) * 16;
    int gr = row0 + ar;

    wmma::fragment<wmma::accumulator, 16, 16, 16, float> acc[FOUT / 16];
    #pragma unroll
    for (int j = 0; j < FOUT / 16; j++) wmma::fill_fragment(acc[j], 0.0f);

    float4 pa_f[4];
    uint4  pa_h[2];
    float4 pb[NBI][2];

    auto loadA = [&](int k0) {
        if (gr < NN) {
            if (AFP32) {
                const float* src = Af32 + (size_t)gr * FIN + k0 + ac0;
                pa_f[0] = *(const float4*)(src + 0);
                pa_f[1] = *(const float4*)(src + 4);
                pa_f[2] = *(const float4*)(src + 8);
                pa_f[3] = *(const float4*)(src + 12);
            } else {
                const uint4* src = (const uint4*)(g_h + (size_t)gr * FIN + k0 + ac0);
                pa_h[0] = src[0];
                pa_h[1] = src[1];
            }
        } else {
            if (AFP32) { pa_f[0] = pa_f[1] = pa_f[2] = pa_f[3] = make_float4(0, 0, 0, 0); }
            else       { pa_h[0] = pa_h[1] = make_uint4(0, 0, 0, 0); }
        }
    };
    auto loadB = [&](int k0) {
        #pragma unroll
        for (int it = 0; it < NBI; it++) {
            int idx = tid + it * 256;
            int r = idx / (FOUT / 8);
            int cb = (idx % (FOUT / 8)) * 8;
            const float* src = W + (size_t)(k0 + r) * FOUT + cb;
            pb[it][0] = *(const float4*)(src + 0);
            pb[it][1] = *(const float4*)(src + 4);
        }
    };
    auto storeA = [&]() {
        uint4 p0, p1;
        if (AFP32) {
            __half2 h0 = __floats2half2_rn(pa_f[0].x, pa_f[0].y), h1 = __floats2half2_rn(pa_f[0].z, pa_f[0].w);
            __half2 h2 = __floats2half2_rn(pa_f[1].x, pa_f[1].y), h3 = __floats2half2_rn(pa_f[1].z, pa_f[1].w);
            __half2 h4 = __floats2half2_rn(pa_f[2].x, pa_f[2].y), h5 = __floats2half2_rn(pa_f[2].z, pa_f[2].w);
            __half2 h6 = __floats2half2_rn(pa_f[3].x, pa_f[3].y), h7 = __floats2half2_rn(pa_f[3].z, pa_f[3].w);
            p0 = make_uint4(*(uint32_t*)&h0, *(uint32_t*)&h1, *(uint32_t*)&h2, *(uint32_t*)&h3);
            p1 = make_uint4(*(uint32_t*)&h4, *(uint32_t*)&h5, *(uint32_t*)&h6, *(uint32_t*)&h7);
        } else {
            p0 = pa_h[0];
            p1 = pa_h[1];
        }
        *(uint4*)&As[ar][ac0]     = p0;
        *(uint4*)&As[ar][ac0 + 8] = p1;
    };
    auto storeB = [&]() {
        #pragma unroll
        for (int it = 0; it < NBI; it++) {
            int idx = tid + it * 256;
            int r = idx / (FOUT / 8);
            int cb = (idx % (FOUT / 8)) * 8;
            __half2 h0 = __floats2half2_rn(pb[it][0].x, pb[it][0].y);
            __half2 h1 = __floats2half2_rn(pb[it][0].z, pb[it][0].w);
            __half2 h2 = __floats2half2_rn(pb[it][1].x, pb[it][1].y);
            __half2 h3 = __floats2half2_rn(pb[it][1].z, pb[it][1].w);
            *(uint4*)&Bs[r][cb] =
                make_uint4(*(uint32_t*)&h0, *(uint32_t*)&h1, *(uint32_t*)&h2, *(uint32_t*)&h3);
        }
    };

    loadA(0);
    loadB(0);

    #pragma unroll
    for (int k0 = 0; k0 < FIN; k0 += 32) {
        storeA();
        storeB();
        __syncthreads();
        if (k0 + 32 < FIN) {
            loadA(k0 + 32);
            loadB(k0 + 32);
        }
        #pragma unroll
        for (int kk = 0; kk < 32; kk += 16) {
            wmma::fragment<wmma::matrix_a, 16, 16, 16, __half, wmma::row_major> af;
            wmma::load_matrix_sync(af, &As[wid * 16][kk], 40);
            #pragma unroll
            for (int j = 0; j < FOUT / 16; j++) {
                wmma::fragment<wmma::matrix_b, 16, 16, 16, __half, wmma::row_major> bf;
                wmma::load_matrix_sync(bf, &Bs[kk][j * 16], FOUT + 8);
                wmma::mma_sync(acc[j], af, bf, acc[j]);
            }
        }
        __syncthreads();
    }

    #pragma unroll
    for (int j = 0; j < FOUT / 16; j++) {
        wmma::store_matrix_sync(&Cs[wid][0][0], acc[j], 20, wmma::mem_row_major);
        __syncwarp();
        int r = lane >> 1, c0 = (lane & 1) * 8;
        int grr = row0 + wid * 16 + r;
        if (grr < NN) {
            const float* s = &Cs[wid][r][c0];
            __half2 h0 = __floats2half2_rn(s[0], s[1]);
            __half2 h1 = __floats2half2_rn(s[2], s[3]);
            __half2 h2 = __floats2half2_rn(s[4], s[5]);
            __half2 h3 = __floats2half2_rn(s[6], s[7]);
            *(uint4*)(g_u + (size_t)grr * FOUT + j * 16 + c0) =
                make_uint4(*(uint32_t*)&h0, *(uint32_t*)&h1, *(uint32_t*)&h2, *(uint32_t*)&h3);
        }
        __syncwarp();
    }
}

// ---------------- CSR gather aggregation (fp16 in/out, fp32 accum) ----------------
__device__ __forceinline__ void acc4(float4& a, uint2 v, float d) {
    float2 f0 = __half22float2(*(__half2*)&v.x);
    float2 f1 = __half22float2(*(__half2*)&v.y);
    a.x = fmaf(f0.x, d, a.x); a.y = fmaf(f0.y, d, a.y);
    a.z = fmaf(f1.x, d, a.z); a.w = fmaf(f1.y, d, a.w);
}

__global__ void k_agg128(const float* __restrict__ bias) {
    int w = (blockIdx.x * blockDim.x + threadIdx.x) >> 5;
    int lane = threadIdx.x & 31;
    if (w >= NN) return;
    const uint2* Uv = (const uint2*)g_u;
    float dd = g_dinv[w];
    float4 acc = make_float4(0.f, 0.f, 0.f, 0.f);
    acc4(acc, Uv[(size_t)w * 32 + lane], dd);
    int e0 = g_rowptr[w], e1 = g_rowptr[w + 1];
    int e = e0;
    for (; e + 4 <= e1; e += 4) {
        int s0 = g_colsrc[e], s1 = g_colsrc[e + 1], s2 = g_colsrc[e + 2], s3 = g_colsrc[e + 3];
        float d0 = g_dinv[s0], d1 = g_dinv[s1], d2 = g_dinv[s2], d3 = g_dinv[s3];
        uint2 v0 = Uv[(size_t)s0 * 32 + lane];
        uint2 v1 = Uv[(size_t)s1 * 32 + lane];
        uint2 v2 = Uv[(size_t)s2 * 32 + lane];
        uint2 v3 = Uv[(size_t)s3 * 32 + lane];
        acc4(acc, v0, d0); acc4(acc, v1, d1); acc4(acc, v2, d2); acc4(acc, v3, d3);
    }
    for (; e < e1; e++) {
        int s = g_colsrc[e];
        acc4(acc, Uv[(size_t)s * 32 + lane], g_dinv[s]);
    }
    float4 bb = ((const float4*)bias)[lane];
    __half2 o0 = __floats2half2_rn(fmaxf(fmaf(acc.x, dd, bb.x), 0.f),
                                   fmaxf(fmaf(acc.y, dd, bb.y), 0.f));
    __half2 o1 = __floats2half2_rn(fmaxf(fmaf(acc.z, dd, bb.z), 0.f),
                                   fmaxf(fmaf(acc.w, dd, bb.w), 0.f));
    ((uint2*)g_h)[(size_t)w * 32 + lane] = make_uint2(*(uint32_t*)&o0, *(uint32_t*)&o1);
}

__global__ void k_agg64(const float* __restrict__ bias) {
    int w = (blockIdx.x * blockDim.x + threadIdx.x) >> 5;
    int lane = threadIdx.x & 31;
    if (w >= NN) return;
    const uint32_t* Uv = (const uint32_t*)g_u;
    float dd = g_dinv[w];
    float2 acc;
    {
        float2 f = __half22float2(*(__half2*)&Uv[(size_t)w * 32 + lane]);
        acc.x = f.x * dd; acc.y = f.y * dd;
    }
    int e0 = g_rowptr[w], e1 = g_rowptr[w + 1];
    int e = e0;
    for (; e + 4 <= e1; e += 4) {
        int s0 = g_colsrc[e], s1 = g_colsrc[e + 1], s2 = g_colsrc[e + 2], s3 = g_colsrc[e + 3];
        float d0 = g_dinv[s0], d1 = g_dinv[s1], d2 = g_dinv[s2], d3 = g_dinv[s3];
        uint32_t v0 = Uv[(size_t)s0 * 32 + lane];
        uint32_t v1 = Uv[(size_t)s1 * 32 + lane];
        uint32_t v2 = Uv[(size_t)s2 * 32 + lane];
        uint32_t v3 = Uv[(size_t)s3 * 32 + lane];
        float2 f0 = __half22float2(*(__half2*)&v0);
        float2 f1 = __half22float2(*(__half2*)&v1);
        float2 f2 = __half22float2(*(__half2*)&v2);
        float2 f3 = __half22float2(*(__half2*)&v3);
        acc.x = fmaf(f0.x, d0, acc.x); acc.y = fmaf(f0.y, d0, acc.y);
        acc.x = fmaf(f1.x, d1, acc.x); acc.y = fmaf(f1.y, d1, acc.y);
        acc.x = fmaf(f2.x, d2, acc.x); acc.y = fmaf(f2.y, d2, acc.y);
        acc.x = fmaf(f3.x, d3, acc.x); acc.y = fmaf(f3.y, d3, acc.y);
    }
    for (; e < e1; e++) {
        int s = g_colsrc[e];
        float2 f = __half22float2(*(__half2*)&Uv[(size_t)s * 32 + lane]);
        float d = g_dinv[s];
        acc.x = fmaf(f.x, d, acc.x); acc.y = fmaf(f.y, d, acc.y);
    }
    float2 bb = ((const float2*)bias)[lane];
    __half2 o = __floats2half2_rn(fmaxf(fmaf(acc.x, dd, bb.x), 0.f),
                                  fmaxf(fmaf(acc.y, dd, bb.y), 0.f));
    ((uint32_t*)g_h)[(size_t)w * 32 + lane] = *(uint32_t*)&o;
}

// ---------------- prototype-distance head + MLP + y copy ----------------
__device__ __forceinline__ float gelu_exact(float x) {
    return 0.5f * x * (1.0f + erff(x * 0.70710678118654752f));
}

__global__ void k_head(const float* __restrict__ prot,
                       const float* __restrict__ Wf0, const float* __restrict__ bf0,
                       const float* __restrict__ Wf1, const float* __restrict__ bf1,
                       const int* __restrict__ y,
                       float* __restrict__ out, int out_size) {
    __shared__ float hs[128][65];
    __shared__ float ps[16][64];
    __shared__ float pn[16];
    __shared__ float w0[16][8];
    __shared__ float b0[8];
    __shared__ float w1[8];
    __shared__ float b1s;

    int t = threadIdx.x;
    int nd0 = blockIdx.x * 128;

    for (int idx = t; idx < 128 * 64; idx += 128) {
        int r = idx >> 6, c = idx & 63;
        int node = nd0 + r;
        hs[r][c] = (node < NN) ? __half2float(g_h[(size_t)node * 64 + c]) : 0.f;
    }
    for (int idx = t; idx < 16 * 64; idx += 128)
        ps[idx >> 6][idx & 63] = prot[idx];
    if (t < 16 * 8) w0[t >> 3][t & 7] = Wf0[t];
    if (t < 8) { b0[t] = bf0[t]; w1[t] = Wf1[t]; }
    if (t == 0) b1s = bf1[0];
    __syncthreads();
    if (t < 16) {
        float s = 0.f;
        #pragma unroll
        for (int c = 0; c < 64; c++) s += ps[t][c] * ps[t][c];
        pn[t] = s;
    }
    __syncthreads();

    int node = nd0 + t;
    if (node < NN) {
        float hh = 0.f;
        #pragma unroll
        for (int c = 0; c < 64; c++) hh = fmaf(hs[t][c], hs[t][c], hh);

        float sim[16];
        #pragma unroll
        for (int k = 0; k < 16; k++) {
            float dot = 0.f;
            #pragma unroll
            for (int c = 0; c < 64; c++) dot = fmaf(hs[t][c], ps[k][c], dot);
            float d2 = fmaxf(hh + pn[k] - 2.0f * dot, 0.f);
            sim[k] = logf((d2 + 1.0f) / (d2 + 1e-4f));
        }

        float o = b1s;
        #pragma unroll
        for (int j = 0; j < 8; j++) {
            float z = b0[j];
            #pragma unroll
            for (int k = 0; k < 16; k++) z = fmaf(sim[k], w0[k][j], z);
            o = fmaf(gelu_exact(z), w1[j], o);
        }
        out[node] = 1.0f / (1.0f + expf(-o));
        if (NN + node < out_size) out[NN + node] = (float)y[node];
    }
}

// ---------------- launch: CSR on s2 concurrent with GEMM1 on main ----------------
extern "C" void kernel_launch(void* const* d_in, const int* in_sizes, int n_in,
                              void* d_out, int out_size) {
    const float* x    = (const float*)d_in[0];
    const int*   ei   = (const int*)d_in[1];
    const int*   y    = (const int*)d_in[2];
    const float* W1   = (const float*)d_in[3];
    const float* b1   = (const float*)d_in[4];
    const float* W2   = (const float*)d_in[5];
    const float* b2   = (const float*)d_in[6];
    const float* W3   = (const float*)d_in[7];
    const float* b3   = (const float*)d_in[8];
    const float* prot = (const float*)d_in[9];
    const float* Wf0  = (const float*)d_in[10];
    const float* bf0  = (const float*)d_in[11];
    const float* Wf1  = (const float*)d_in[12];
    const float* bf1  = (const float*)d_in[13];
    float* out = (float*)d_out;

    // one-time resources (created on the uncaptured correctness call)
    static cudaStream_t s2 = nullptr;
    static cudaEvent_t evFork = nullptr, evJoin = nullptr;
    static void* cntPtr = nullptr;
    if (!s2) {
        cudaStreamCreateWithFlags(&s2, cudaStreamNonBlocking);
        cudaEventCreateWithFlags(&evFork, cudaEventDisableTiming);
        cudaEventCreateWithFlags(&evJoin, cudaEventDisableTiming);
        cudaGetSymbolAddress(&cntPtr, g_cnt);
    }

    const int MT = (NN + 127) / 128;  // 391 M-tiles
    int aggBlocks = (NN * 32 + 255) / 256;

    // fork: CSR build on s2
    cudaEventRecord(evFork, 0);
    cudaStreamWaitEvent(s2, evFork, 0);
    cudaMemsetAsync(cntPtr, 0, sizeof(int) * NN, s2);
    k_count<<<(NE + 255) / 256, 256, 0, s2>>>(ei);
    k_scan1<<<SCAN_NB, SCAN_B, 0, s2>>>();
    k_scan3<<<SCAN_NB, SCAN_B, 0, s2>>>();
    k_scatter<<<(NE + 255) / 256, 256, 0, s2>>>(ei);
    cudaEventRecord(evJoin, s2);

    // concurrent: layer-1 GEMM on main stream (independent of CSR)
    k_gemm_wmma<128, 128, true><<<MT, 256>>>(x, W1);

    cudaStreamWaitEvent(0, evJoin, 0);  // join

    // layer 1 agg -> layer 2 -> layer 3 -> head
    k_agg128<<<aggBlocks, 256>>>(b1);
    k_gemm_wmma<128, 64, false><<<MT, 256>>>(nullptr, W2);
    k_agg64<<<aggBlocks, 256>>>(b2);
    k_gemm_wmma<64, 64, false><<<MT, 256>>>(nullptr, W3);
    k_agg64<<<aggBlocks, 256>>>(b3);
    k_head<<<(NN + 127) / 128, 128>>>(prot, Wf0, bf0, Wf1, bf1, y, out, out_size);
}